// round 1
// baseline (speedup 1.0000x reference)
#include <cuda_runtime.h>
#include <cuda_bf16.h>
#include <cstdint>

#define NN 100000
#define EE 1600000
#define IN_DIM 128
#define HH 64
#define GG 64
#define LN_EPS 1e-5f

// ---------------- device scratch (no allocation allowed) ----------------
__device__ float g_deg[NN];          // degree accumulator
__device__ float g_di[NN];           // deg^{-1/2}
__device__ float g_norm[EE];         // per-edge norm = di[src]*di[dst]
__device__ float g_bufA[(size_t)NN * HH];
__device__ float g_bufB[(size_t)NN * HH];
__device__ float g_s3[NN];           // h_lin of layer 3 (scalar)
__device__ float g_pool[2 * GG];     // sums[G], counts[G]

// ---------------- setup kernels ----------------
__global__ void k_zero() {
    int i = blockIdx.x * blockDim.x + threadIdx.x;
    if (i < NN) g_deg[i] = 0.0f;
    if (i < 2 * GG) g_pool[i] = 0.0f;
}

__global__ void k_count(const int* __restrict__ dst) {
    int e = blockIdx.x * blockDim.x + threadIdx.x;
    if (e < EE) atomicAdd(&g_deg[dst[e]], 1.0f);
}

__global__ void k_isqrt() {
    int i = blockIdx.x * blockDim.x + threadIdx.x;
    if (i < NN) g_di[i] = rsqrtf(g_deg[i] + 1.0f);
}

__global__ void k_norm(const int* __restrict__ src, const int* __restrict__ dst) {
    int e = blockIdx.x * blockDim.x + threadIdx.x;
    if (e < EE) g_norm[e] = g_di[src[e]] * g_di[dst[e]];
}

// ---------------- GEMM: Y[N][64] = X[N][K] @ W[K][64] ----------------
// 64x64 output tile per block, 256 threads, each thread 4 rows x 4 cols,
// K chunked by 64 to stay under 48KB static smem.
template <int K>
__global__ __launch_bounds__(256) void k_gemm(const float* __restrict__ X,
                                              const float* __restrict__ W,
                                              float* __restrict__ Y) {
    __shared__ float  Xs[64][68];     // 64 rows x 64-k chunk (+4 pad)
    __shared__ float4 Ws[64][16];     // 64-k chunk x 64 cols (as float4)
    const int tid  = threadIdx.x;
    const int row0 = blockIdx.x * 64;
    const int tx = tid & 15;          // col group (4 cols)
    const int ty = tid >> 4;          // row group (4 rows)

    float4 acc[4];
    #pragma unroll
    for (int r = 0; r < 4; r++) acc[r] = make_float4(0.f, 0.f, 0.f, 0.f);

    for (int kk = 0; kk < K; kk += 64) {
        // load W chunk: 64x64 floats = 1024 float4
        #pragma unroll
        for (int i = tid; i < 1024; i += 256) {
            int k = i >> 4, c = i & 15;
            Ws[k][c] = reinterpret_cast<const float4*>(W)[(size_t)(kk + k) * 16 + c];
        }
        // load X chunk: 64 rows x 16 float4
        #pragma unroll
        for (int i = tid; i < 1024; i += 256) {
            int r = i >> 4, kv = i & 15;
            int row = row0 + r;
            float4 v = make_float4(0.f, 0.f, 0.f, 0.f);
            if (row < NN)
                v = reinterpret_cast<const float4*>(X)[(size_t)row * (K / 4) + (kk / 4) + kv];
            *reinterpret_cast<float4*>(&Xs[r][kv * 4]) = v;
        }
        __syncthreads();

        #pragma unroll 16
        for (int k = 0; k < 64; k++) {
            float4 w = Ws[k][tx];
            #pragma unroll
            for (int r = 0; r < 4; r++) {
                float xv = Xs[ty * 4 + r][k];
                acc[r].x = fmaf(xv, w.x, acc[r].x);
                acc[r].y = fmaf(xv, w.y, acc[r].y);
                acc[r].z = fmaf(xv, w.z, acc[r].z);
                acc[r].w = fmaf(xv, w.w, acc[r].w);
            }
        }
        __syncthreads();
    }

    #pragma unroll
    for (int r = 0; r < 4; r++) {
        int row = row0 + ty * 4 + r;
        if (row < NN)
            reinterpret_cast<float4*>(Y)[(size_t)row * 16 + tx] = acc[r];
    }
}

// ---------------- agg init: agg = h_lin * (1/deg) + b ----------------
__global__ void k_init_agg(const float* __restrict__ lin, float* __restrict__ agg,
                           const float* __restrict__ b) {
    int idx = blockIdx.x * blockDim.x + threadIdx.x;
    if (idx >= NN * HH) return;
    int i = idx >> 6;
    int f = idx & 63;
    float d = g_di[i];
    agg[idx] = fmaf(lin[idx], d * d, b[f]);
}

// ---------------- edge scatter, 64 features ----------------
// warp = 2 edges; 16 lanes per edge, each lane one float4 (4 feats)
__global__ __launch_bounds__(256) void k_scatter64(const float* __restrict__ hlin,
                                                   float* __restrict__ agg,
                                                   const int* __restrict__ src,
                                                   const int* __restrict__ dst) {
    int t = blockIdx.x * blockDim.x + threadIdx.x;
    int e = t >> 4;
    if (e >= EE) return;
    int f4 = t & 15;
    int s = src[e];
    int d = dst[e];
    float nv = g_norm[e];
    float4 v = reinterpret_cast<const float4*>(hlin)[(size_t)s * 16 + f4];
    float4 m = make_float4(v.x * nv, v.y * nv, v.z * nv, v.w * nv);
    atomicAdd(reinterpret_cast<float4*>(agg) + (size_t)d * 16 + f4, m); // -> RED.v4
}

// ---------------- layernorm(64) + relu, warp per row ----------------
__global__ void k_ln_relu(const float* __restrict__ Xin, float* __restrict__ Yout,
                          const float* __restrict__ gam, const float* __restrict__ bet) {
    int warp = (blockIdx.x * blockDim.x + threadIdx.x) >> 5;
    int lane = threadIdx.x & 31;
    if (warp >= NN) return;
    const float* r = Xin + (size_t)warp * 64;
    float v0 = r[lane];
    float v1 = r[lane + 32];
    float s = v0 + v1;
    float q = v0 * v0 + v1 * v1;
    #pragma unroll
    for (int o = 16; o > 0; o >>= 1) {
        s += __shfl_xor_sync(0xffffffffu, s, o);
        q += __shfl_xor_sync(0xffffffffu, q, o);
    }
    float mu  = s * (1.0f / 64.0f);
    float var = q * (1.0f / 64.0f) - mu * mu;
    float rs  = rsqrtf(var + LN_EPS);
    float y0 = fmaxf(fmaf((v0 - mu) * rs, gam[lane], bet[lane]), 0.0f);
    float y1 = fmaxf(fmaf((v1 - mu) * rs, gam[lane + 32], bet[lane + 32]), 0.0f);
    float* w = Yout + (size_t)warp * 64;
    w[lane] = y0;
    w[lane + 32] = y1;
}

// ---------------- layer 3: s3 = h2 @ W3 ; out = s3/deg + b3 ----------------
__global__ void k_dot_init(const float* __restrict__ h2, const float* __restrict__ W3,
                           const float* __restrict__ b3, float* __restrict__ out) {
    int warp = (blockIdx.x * blockDim.x + threadIdx.x) >> 5;
    int lane = threadIdx.x & 31;
    if (warp >= NN) return;
    const float* r = h2 + (size_t)warp * 64;
    float p = r[lane] * W3[lane] + r[lane + 32] * W3[lane + 32];
    #pragma unroll
    for (int o = 16; o > 0; o >>= 1) p += __shfl_xor_sync(0xffffffffu, p, o);
    if (lane == 0) {
        g_s3[warp] = p;
        float d = g_di[warp];
        out[warp] = fmaf(p, d * d, b3[0]);
    }
}

__global__ void k_scatter1(const int* __restrict__ src, const int* __restrict__ dst,
                           float* __restrict__ out) {
    int e = blockIdx.x * blockDim.x + threadIdx.x;
    if (e >= EE) return;
    atomicAdd(&out[dst[e]], g_s3[src[e]] * g_norm[e]);
}

// ---------------- mean pooling over (sorted) batch ----------------
__global__ void k_pool(const int* __restrict__ batch, const float* __restrict__ out) {
    __shared__ float ss[GG];
    __shared__ float sc[GG];
    int tid = threadIdx.x;
    if (tid < GG) { ss[tid] = 0.0f; sc[tid] = 0.0f; }
    __syncthreads();
    int i = blockIdx.x * blockDim.x + tid;
    if (i < NN) {
        int g = batch[i];
        atomicAdd(&ss[g], out[i]);
        atomicAdd(&sc[g], 1.0f);
    }
    __syncthreads();
    if (tid < GG) {
        if (ss[tid] != 0.0f || sc[tid] != 0.0f) {
            atomicAdd(&g_pool[tid], ss[tid]);
            atomicAdd(&g_pool[GG + tid], sc[tid]);
        }
    }
}

__global__ void k_final(const float* __restrict__ Wg, const float* __restrict__ bg,
                        float* __restrict__ out) {
    int g = threadIdx.x;
    if (g < GG) {
        float s = g_pool[g];
        float c = g_pool[GG + g];
        float p = s / fmaxf(c, 1.0f);
        out[NN + g] = fmaf(p, Wg[0], bg[0]);
    }
}

// ---------------- launcher ----------------
extern "C" void kernel_launch(void* const* d_in, const int* in_sizes, int n_in,
                              void* d_out, int out_size) {
    const float* x    = (const float*)d_in[0];
    const int*   ei   = (const int*)d_in[1];
    const int*   batch= (const int*)d_in[2];
    const float* W1   = (const float*)d_in[3];
    const float* b1   = (const float*)d_in[4];
    const float* g1   = (const float*)d_in[5];
    const float* be1  = (const float*)d_in[6];
    const float* W2   = (const float*)d_in[7];
    const float* b2   = (const float*)d_in[8];
    const float* g2   = (const float*)d_in[9];
    const float* be2  = (const float*)d_in[10];
    const float* W3   = (const float*)d_in[11];
    const float* b3   = (const float*)d_in[12];
    const float* Wg   = (const float*)d_in[13];
    const float* bg   = (const float*)d_in[14];
    const int* src = ei;
    const int* dst = ei + EE;
    float* out = (float*)d_out;

    float *bufA, *bufB;
    cudaGetSymbolAddress((void**)&bufA, g_bufA);
    cudaGetSymbolAddress((void**)&bufB, g_bufB);

    const int TB = 256;
    const int nblkN  = (NN + TB - 1) / TB;            // 391
    const int nblkE  = (EE + TB - 1) / TB;            // 6250
    const int nblkNH = (NN * HH + TB - 1) / TB;       // 25000
    const int nblkW  = (NN * 32 + TB - 1) / TB;       // warp-per-row kernels: 12500
    const int nblkS  = (EE * 16) / TB;                // scatter64: 100000
    const int nblkG  = (NN + 63) / 64;                // gemm: 1563

    // degrees + norms
    k_zero <<<nblkN, TB>>>();
    k_count<<<nblkE, TB>>>(dst);
    k_isqrt<<<nblkN, TB>>>();
    k_norm <<<nblkE, TB>>>(src, dst);

    // layer 1
    k_gemm<IN_DIM><<<nblkG, TB>>>(x, W1, bufA);
    k_init_agg<<<nblkNH, TB>>>(bufA, bufB, b1);
    k_scatter64<<<nblkS, TB>>>(bufA, bufB, src, dst);
    k_ln_relu<<<nblkW, TB>>>(bufB, bufA, g1, be1);

    // layer 2
    k_gemm<HH><<<nblkG, TB>>>(bufA, W2, bufB);
    k_init_agg<<<nblkNH, TB>>>(bufB, bufA, b2);
    k_scatter64<<<nblkS, TB>>>(bufB, bufA, src, dst);
    k_ln_relu<<<nblkW, TB>>>(bufA, bufB, g2, be2);

    // layer 3 (scalar) + pooling
    k_dot_init<<<nblkW, TB>>>(bufB, W3, b3, out);
    k_scatter1<<<nblkE, TB>>>(src, dst, out);
    k_pool<<<nblkN, TB>>>(batch, out);
    k_final<<<1, 64>>>(Wg, bg, out);
}

// round 2
// speedup vs baseline: 1.4683x; 1.4683x over previous
#include <cuda_runtime.h>
#include <cuda_bf16.h>
#include <cstdint>

#define NN 100000
#define EE 1600000
#define IN_DIM 128
#define HH 64
#define GG 64
#define LN_EPS 1e-5f
#define NBLK_N 391   // ceil(NN/256)

// ---------------- device scratch ----------------
__device__ int   g_cnt[NN];        // in-degree counts
__device__ int   g_rowstart[NN];   // CSR row offsets (by dst)
__device__ int   g_cur[NN];        // fill cursors
__device__ int   g_csrc[EE];       // CSR column indices (src per dst-slot)
__device__ int   g_bsum[512];      // block sums for scan
__device__ float g_di[NN];         // deg^{-1/2}
__device__ float g_bufA[(size_t)NN * HH];
__device__ float g_bufB[(size_t)NN * HH];
__device__ float g_s3[NN];         // di-scaled layer-3 linear output
__device__ float g_pool[2 * GG];

// ---------------- setup ----------------
__global__ void k_zero() {
    int i = blockIdx.x * blockDim.x + threadIdx.x;
    if (i < NN) g_cnt[i] = 0;
    if (i < 2 * GG) g_pool[i] = 0.0f;
}

__global__ void k_count(const int* __restrict__ dst) {
    int e = blockIdx.x * blockDim.x + threadIdx.x;
    if (e < EE) atomicAdd(&g_cnt[dst[e]], 1);
}

__global__ void k_isqrt() {
    int i = blockIdx.x * blockDim.x + threadIdx.x;
    if (i < NN) g_di[i] = rsqrtf((float)g_cnt[i] + 1.0f);
}

// ---- 2-level exclusive scan of g_cnt -> g_rowstart (and g_cur) ----
__global__ void k_blocksum() {
    __shared__ int s[256];
    int i = blockIdx.x * 256 + threadIdx.x;
    s[threadIdx.x] = (i < NN) ? g_cnt[i] : 0;
    __syncthreads();
    for (int o = 128; o > 0; o >>= 1) {
        if (threadIdx.x < o) s[threadIdx.x] += s[threadIdx.x + o];
        __syncthreads();
    }
    if (threadIdx.x == 0) g_bsum[blockIdx.x] = s[0];
}

__global__ void k_scanblk() {   // 1 block, 512 threads: exclusive scan of NBLK_N partials
    __shared__ int s[512];
    int t = threadIdx.x;
    int own = (t < NBLK_N) ? g_bsum[t] : 0;
    s[t] = own;
    __syncthreads();
    for (int o = 1; o < 512; o <<= 1) {
        int v = (t >= o) ? s[t - o] : 0;
        __syncthreads();
        s[t] += v;
        __syncthreads();
    }
    if (t < NBLK_N) g_bsum[t] = s[t] - own;   // exclusive
}

__global__ void k_rowstart() {
    __shared__ int s[256];
    int i = blockIdx.x * 256 + threadIdx.x;
    int c = (i < NN) ? g_cnt[i] : 0;
    s[threadIdx.x] = c;
    __syncthreads();
    for (int o = 1; o < 256; o <<= 1) {
        int v = (threadIdx.x >= o) ? s[threadIdx.x - o] : 0;
        __syncthreads();
        s[threadIdx.x] += v;
        __syncthreads();
    }
    int excl = s[threadIdx.x] - c + g_bsum[blockIdx.x];
    if (i < NN) { g_rowstart[i] = excl; g_cur[i] = excl; }
}

__global__ void k_fill(const int* __restrict__ src, const int* __restrict__ dst) {
    int e = blockIdx.x * blockDim.x + threadIdx.x;
    if (e < EE) {
        int d = dst[e];
        int pos = atomicAdd(&g_cur[d], 1);
        g_csrc[pos] = src[e];
    }
}

// ---------------- GEMM: Y[N][64] = di[row] * (X[N][K] @ W[K][64]) ----------------
template <int K>
__global__ __launch_bounds__(256) void k_gemm(const float* __restrict__ X,
                                              const float* __restrict__ W,
                                              float* __restrict__ Y) {
    __shared__ float  Xs[64][68];
    __shared__ float4 Ws[64][16];
    const int tid  = threadIdx.x;
    const int row0 = blockIdx.x * 64;
    const int tx = tid & 15;
    const int ty = tid >> 4;

    float4 acc[4];
    #pragma unroll
    for (int r = 0; r < 4; r++) acc[r] = make_float4(0.f, 0.f, 0.f, 0.f);

    for (int kk = 0; kk < K; kk += 64) {
        #pragma unroll
        for (int i = tid; i < 1024; i += 256) {
            int k = i >> 4, c = i & 15;
            Ws[k][c] = reinterpret_cast<const float4*>(W)[(size_t)(kk + k) * 16 + c];
        }
        #pragma unroll
        for (int i = tid; i < 1024; i += 256) {
            int r = i >> 4, kv = i & 15;
            int row = row0 + r;
            float4 v = make_float4(0.f, 0.f, 0.f, 0.f);
            if (row < NN)
                v = reinterpret_cast<const float4*>(X)[(size_t)row * (K / 4) + (kk / 4) + kv];
            *reinterpret_cast<float4*>(&Xs[r][kv * 4]) = v;
        }
        __syncthreads();

        #pragma unroll 16
        for (int k = 0; k < 64; k++) {
            float4 w = Ws[k][tx];
            #pragma unroll
            for (int r = 0; r < 4; r++) {
                float xv = Xs[ty * 4 + r][k];
                acc[r].x = fmaf(xv, w.x, acc[r].x);
                acc[r].y = fmaf(xv, w.y, acc[r].y);
                acc[r].z = fmaf(xv, w.z, acc[r].z);
                acc[r].w = fmaf(xv, w.w, acc[r].w);
            }
        }
        __syncthreads();
    }

    #pragma unroll
    for (int r = 0; r < 4; r++) {
        int row = row0 + ty * 4 + r;
        if (row < NN) {
            float d = g_di[row];
            float4 a = acc[r];
            a.x *= d; a.y *= d; a.z *= d; a.w *= d;
            reinterpret_cast<float4*>(Y)[(size_t)row * 16 + tx] = a;
        }
    }
}

// ---------------- fused gather + self + di-postscale + bias + LN + ReLU ----------------
// warp per dst node; lane owns features (lane) and (lane+32)
__global__ __launch_bounds__(256) void k_agg_ln(const float* __restrict__ hs,
                                                float* __restrict__ Yout,
                                                const float* __restrict__ b,
                                                const float* __restrict__ gam,
                                                const float* __restrict__ bet) {
    int warp = (blockIdx.x * blockDim.x + threadIdx.x) >> 5;
    int lane = threadIdx.x & 31;
    if (warp >= NN) return;

    const int start = g_rowstart[warp];
    const int n     = g_cnt[warp];

    // self term
    float a0 = hs[(size_t)warp * 64 + lane];
    float a1 = hs[(size_t)warp * 64 + lane + 32];

    int j = 0;
    while (j + 32 <= n) {
        int idx = g_csrc[start + j + lane];
        #pragma unroll 8
        for (int t = 0; t < 32; t++) {
            int s = __shfl_sync(0xffffffffu, idx, t);
            a0 += hs[(size_t)s * 64 + lane];
            a1 += hs[(size_t)s * 64 + lane + 32];
        }
        j += 32;
    }
    if (j < n) {
        int m = n - j;
        int idx = (j + lane < n) ? g_csrc[start + j + lane] : 0;
        #pragma unroll 4
        for (int t = 0; t < m; t++) {
            int s = __shfl_sync(0xffffffffu, idx, t);
            a0 += hs[(size_t)s * 64 + lane];
            a1 += hs[(size_t)s * 64 + lane + 32];
        }
    }

    float dd = g_di[warp];
    float x0 = fmaf(dd, a0, b[lane]);
    float x1 = fmaf(dd, a1, b[lane + 32]);

    float s  = x0 + x1;
    float q  = x0 * x0 + x1 * x1;
    #pragma unroll
    for (int o = 16; o > 0; o >>= 1) {
        s += __shfl_xor_sync(0xffffffffu, s, o);
        q += __shfl_xor_sync(0xffffffffu, q, o);
    }
    float mu  = s * (1.0f / 64.0f);
    float var = q * (1.0f / 64.0f) - mu * mu;
    float rs  = rsqrtf(var + LN_EPS);
    float y0 = fmaxf(fmaf((x0 - mu) * rs, gam[lane], bet[lane]), 0.0f);
    float y1 = fmaxf(fmaf((x1 - mu) * rs, gam[lane + 32], bet[lane + 32]), 0.0f);
    float* w = Yout + (size_t)warp * 64;
    w[lane]      = y0;
    w[lane + 32] = y1;
}

// ---------------- layer 3: s3 = di * (h2 @ W3) ----------------
__global__ void k_dot(const float* __restrict__ h2, const float* __restrict__ W3) {
    int warp = (blockIdx.x * blockDim.x + threadIdx.x) >> 5;
    int lane = threadIdx.x & 31;
    if (warp >= NN) return;
    const float* r = h2 + (size_t)warp * 64;
    float p = r[lane] * W3[lane] + r[lane + 32] * W3[lane + 32];
    #pragma unroll
    for (int o = 16; o > 0; o >>= 1) p += __shfl_xor_sync(0xffffffffu, p, o);
    if (lane == 0) g_s3[warp] = p * g_di[warp];
}

// out[i] = di[i] * (sum_neighbors s3[src] + s3[i]) + b3
__global__ void k_agg3(const float* __restrict__ b3, float* __restrict__ out) {
    int warp = (blockIdx.x * blockDim.x + threadIdx.x) >> 5;
    int lane = threadIdx.x & 31;
    if (warp >= NN) return;
    int start = g_rowstart[warp];
    int n     = g_cnt[warp];
    float acc = 0.0f;
    for (int j = lane; j < n; j += 32)
        acc += g_s3[g_csrc[start + j]];
    #pragma unroll
    for (int o = 16; o > 0; o >>= 1) acc += __shfl_xor_sync(0xffffffffu, acc, o);
    if (lane == 0)
        out[warp] = fmaf(g_di[warp], acc + g_s3[warp], b3[0]);
}

// ---------------- mean pooling ----------------
__global__ void k_pool(const int* __restrict__ batch, const float* __restrict__ out) {
    __shared__ float ss[GG];
    __shared__ float sc[GG];
    int tid = threadIdx.x;
    if (tid < GG) { ss[tid] = 0.0f; sc[tid] = 0.0f; }
    __syncthreads();
    int i = blockIdx.x * blockDim.x + tid;
    if (i < NN) {
        int g = batch[i];
        atomicAdd(&ss[g], out[i]);
        atomicAdd(&sc[g], 1.0f);
    }
    __syncthreads();
    if (tid < GG) {
        if (ss[tid] != 0.0f || sc[tid] != 0.0f) {
            atomicAdd(&g_pool[tid], ss[tid]);
            atomicAdd(&g_pool[GG + tid], sc[tid]);
        }
    }
}

__global__ void k_final(const float* __restrict__ Wg, const float* __restrict__ bg,
                        float* __restrict__ out) {
    int g = threadIdx.x;
    if (g < GG) {
        float s = g_pool[g];
        float c = g_pool[GG + g];
        float p = s / fmaxf(c, 1.0f);
        out[NN + g] = fmaf(p, Wg[0], bg[0]);
    }
}

// ---------------- launcher ----------------
extern "C" void kernel_launch(void* const* d_in, const int* in_sizes, int n_in,
                              void* d_out, int out_size) {
    const float* x    = (const float*)d_in[0];
    const int*   ei   = (const int*)d_in[1];
    const int*   batch= (const int*)d_in[2];
    const float* W1   = (const float*)d_in[3];
    const float* b1   = (const float*)d_in[4];
    const float* g1   = (const float*)d_in[5];
    const float* be1  = (const float*)d_in[6];
    const float* W2   = (const float*)d_in[7];
    const float* b2   = (const float*)d_in[8];
    const float* g2   = (const float*)d_in[9];
    const float* be2  = (const float*)d_in[10];
    const float* W3   = (const float*)d_in[11];
    const float* b3   = (const float*)d_in[12];
    const float* Wg   = (const float*)d_in[13];
    const float* bg   = (const float*)d_in[14];
    const int* src = ei;
    const int* dst = ei + EE;
    float* out = (float*)d_out;

    float *bufA, *bufB;
    cudaGetSymbolAddress((void**)&bufA, g_bufA);
    cudaGetSymbolAddress((void**)&bufB, g_bufB);

    const int TB = 256;
    const int nblkN = NBLK_N;                // 391
    const int nblkE = (EE + TB - 1) / TB;    // 6250
    const int nblkW = (NN * 32 + TB - 1) / TB; // 12500 warp-per-node
    const int nblkG = (NN + 63) / 64;        // 1563

    // degrees + CSR
    k_zero     <<<nblkN, TB>>>();
    k_count    <<<nblkE, TB>>>(dst);
    k_isqrt    <<<nblkN, TB>>>();
    k_blocksum <<<nblkN, 256>>>();
    k_scanblk  <<<1, 512>>>();
    k_rowstart <<<nblkN, 256>>>();
    k_fill     <<<nblkE, TB>>>(src, dst);

    // layer 1
    k_gemm<IN_DIM><<<nblkG, TB>>>(x, W1, bufA);
    k_agg_ln      <<<nblkW, TB>>>(bufA, bufB, b1, g1, be1);

    // layer 2
    k_gemm<HH><<<nblkG, TB>>>(bufB, W2, bufA);
    k_agg_ln  <<<nblkW, TB>>>(bufA, bufB, b2, g2, be2);

    // layer 3 + pooling
    k_dot  <<<nblkW, TB>>>(bufB, W3);
    k_agg3 <<<nblkW, TB>>>(b3, out);
    k_pool <<<nblkN, TB>>>(batch, out);
    k_final<<<1, 64>>>(Wg, bg, out);
}

// round 3
// speedup vs baseline: 1.5542x; 1.0585x over previous
#include <cuda_runtime.h>
#include <cuda_bf16.h>
#include <cstdint>

#define NN 100000
#define EE 1600000
#define IN_DIM 128
#define HH 64
#define GG 64
#define LN_EPS 1e-5f
#define NBLK_N 391   // ceil(NN/256)

// ---------------- device scratch ----------------
__device__ int   g_cnt[NN];        // in-degree counts
__device__ int   g_rowstart[NN];   // CSR row offsets (by dst)
__device__ int   g_cur[NN];        // fill cursors
__device__ int   g_csrc[EE];       // CSR column indices (src per dst-slot)
__device__ int   g_bsum[512];      // block sums for scan
__device__ float g_di[NN];         // deg^{-1/2}
__device__ float g_bufA[(size_t)NN * HH];
__device__ float g_bufB[(size_t)NN * HH];
__device__ float g_s3[NN];         // di-scaled layer-3 linear output
__device__ float g_pool[2 * GG];

// ---------------- setup ----------------
__global__ void k_count(const int* __restrict__ dst) {
    int e = blockIdx.x * blockDim.x + threadIdx.x;
    if (e < EE) atomicAdd(&g_cnt[dst[e]], 1);
}

__global__ void k_isqrt() {
    int i = blockIdx.x * blockDim.x + threadIdx.x;
    if (i < NN) g_di[i] = rsqrtf((float)g_cnt[i] + 1.0f);
}

// ---- 2-level exclusive scan of g_cnt -> g_rowstart (and g_cur) ----
__global__ void k_blocksum() {
    __shared__ int s[256];
    int i = blockIdx.x * 256 + threadIdx.x;
    s[threadIdx.x] = (i < NN) ? g_cnt[i] : 0;
    __syncthreads();
    for (int o = 128; o > 0; o >>= 1) {
        if (threadIdx.x < o) s[threadIdx.x] += s[threadIdx.x + o];
        __syncthreads();
    }
    if (threadIdx.x == 0) g_bsum[blockIdx.x] = s[0];
}

__global__ void k_scanblk() {   // 1 block, 512 threads
    __shared__ int s[512];
    int t = threadIdx.x;
    int own = (t < NBLK_N) ? g_bsum[t] : 0;
    s[t] = own;
    __syncthreads();
    for (int o = 1; o < 512; o <<= 1) {
        int v = (t >= o) ? s[t - o] : 0;
        __syncthreads();
        s[t] += v;
        __syncthreads();
    }
    if (t < NBLK_N) g_bsum[t] = s[t] - own;   // exclusive
}

__global__ void k_rowstart() {
    __shared__ int s[256];
    int i = blockIdx.x * 256 + threadIdx.x;
    int c = (i < NN) ? g_cnt[i] : 0;
    s[threadIdx.x] = c;
    __syncthreads();
    for (int o = 1; o < 256; o <<= 1) {
        int v = (threadIdx.x >= o) ? s[threadIdx.x - o] : 0;
        __syncthreads();
        s[threadIdx.x] += v;
        __syncthreads();
    }
    int excl = s[threadIdx.x] - c + g_bsum[blockIdx.x];
    if (i < NN) { g_rowstart[i] = excl; g_cur[i] = excl; }
}

__global__ void k_fill(const int* __restrict__ src, const int* __restrict__ dst) {
    int e = blockIdx.x * blockDim.x + threadIdx.x;
    if (e < EE) {
        int d = dst[e];
        int pos = atomicAdd(&g_cur[d], 1);
        g_csrc[pos] = src[e];
    }
}

// ---------------- GEMM: Y[N][64] = di[row] * (X[N][K] @ W[K][64]) ----------------
template <int K>
__global__ __launch_bounds__(256) void k_gemm(const float* __restrict__ X,
                                              const float* __restrict__ W,
                                              float* __restrict__ Y) {
    __shared__ float  Xs[64][68];
    __shared__ float4 Ws[64][16];
    const int tid  = threadIdx.x;
    const int row0 = blockIdx.x * 64;
    const int tx = tid & 15;
    const int ty = tid >> 4;

    float4 acc[4];
    #pragma unroll
    for (int r = 0; r < 4; r++) acc[r] = make_float4(0.f, 0.f, 0.f, 0.f);

    for (int kk = 0; kk < K; kk += 64) {
        #pragma unroll
        for (int i = tid; i < 1024; i += 256) {
            int k = i >> 4, c = i & 15;
            Ws[k][c] = reinterpret_cast<const float4*>(W)[(size_t)(kk + k) * 16 + c];
        }
        #pragma unroll
        for (int i = tid; i < 1024; i += 256) {
            int r = i >> 4, kv = i & 15;
            int row = row0 + r;
            float4 v = make_float4(0.f, 0.f, 0.f, 0.f);
            if (row < NN)
                v = reinterpret_cast<const float4*>(X)[(size_t)row * (K / 4) + (kk / 4) + kv];
            *reinterpret_cast<float4*>(&Xs[r][kv * 4]) = v;
        }
        __syncthreads();

        #pragma unroll 16
        for (int k = 0; k < 64; k++) {
            float4 w = Ws[k][tx];
            #pragma unroll
            for (int r = 0; r < 4; r++) {
                float xv = Xs[ty * 4 + r][k];
                acc[r].x = fmaf(xv, w.x, acc[r].x);
                acc[r].y = fmaf(xv, w.y, acc[r].y);
                acc[r].z = fmaf(xv, w.z, acc[r].z);
                acc[r].w = fmaf(xv, w.w, acc[r].w);
            }
        }
        __syncthreads();
    }

    #pragma unroll
    for (int r = 0; r < 4; r++) {
        int row = row0 + ty * 4 + r;
        if (row < NN) {
            float d = g_di[row];
            float4 a = acc[r];
            a.x *= d; a.y *= d; a.z *= d; a.w *= d;
            reinterpret_cast<float4*>(Y)[(size_t)row * 16 + tx] = a;
        }
    }
}

// ------- fused gather + self + di-postscale + bias + LN + ReLU (+ optional W3 dot) -------
// warp per dst node; lane owns features (lane) and (lane+32)
template <bool FUSE_DOT>
__global__ __launch_bounds__(256) void k_agg_ln(const float* __restrict__ hs,
                                                float* __restrict__ Yout,
                                                const float* __restrict__ b,
                                                const float* __restrict__ gam,
                                                const float* __restrict__ bet,
                                                const float* __restrict__ W3) {
    int warp = (blockIdx.x * blockDim.x + threadIdx.x) >> 5;
    int lane = threadIdx.x & 31;
    if (warp >= NN) return;

    const int start = g_rowstart[warp];
    const int n     = g_cnt[warp];

    float a0 = hs[(size_t)warp * 64 + lane];
    float a1 = hs[(size_t)warp * 64 + lane + 32];

    int j = 0;
    while (j + 32 <= n) {
        int idx = g_csrc[start + j + lane];
        #pragma unroll 8
        for (int t = 0; t < 32; t++) {
            int s = __shfl_sync(0xffffffffu, idx, t);
            a0 += hs[(size_t)s * 64 + lane];
            a1 += hs[(size_t)s * 64 + lane + 32];
        }
        j += 32;
    }
    if (j < n) {
        int m = n - j;
        int idx = (j + lane < n) ? g_csrc[start + j + lane] : 0;
        #pragma unroll 4
        for (int t = 0; t < m; t++) {
            int s = __shfl_sync(0xffffffffu, idx, t);
            a0 += hs[(size_t)s * 64 + lane];
            a1 += hs[(size_t)s * 64 + lane + 32];
        }
    }

    float dd = g_di[warp];
    float x0 = fmaf(dd, a0, b[lane]);
    float x1 = fmaf(dd, a1, b[lane + 32]);

    float s  = x0 + x1;
    float q  = x0 * x0 + x1 * x1;
    #pragma unroll
    for (int o = 16; o > 0; o >>= 1) {
        s += __shfl_xor_sync(0xffffffffu, s, o);
        q += __shfl_xor_sync(0xffffffffu, q, o);
    }
    float mu  = s * (1.0f / 64.0f);
    float var = q * (1.0f / 64.0f) - mu * mu;
    float rs  = rsqrtf(var + LN_EPS);
    float y0 = fmaxf(fmaf((x0 - mu) * rs, gam[lane], bet[lane]), 0.0f);
    float y1 = fmaxf(fmaf((x1 - mu) * rs, gam[lane + 32], bet[lane + 32]), 0.0f);

    if (FUSE_DOT) {
        // layer-3 linear: s3 = di * (y . W3); never materialize y
        float p = y0 * W3[lane] + y1 * W3[lane + 32];
        #pragma unroll
        for (int o = 16; o > 0; o >>= 1) p += __shfl_xor_sync(0xffffffffu, p, o);
        if (lane == 0) g_s3[warp] = p * dd;
    } else {
        float* w = Yout + (size_t)warp * 64;
        w[lane]      = y0;
        w[lane + 32] = y1;
    }
}

// out[i] = di[i] * (sum_neighbors s3[src] + s3[i]) + b3
__global__ void k_agg3(const float* __restrict__ b3, float* __restrict__ out) {
    int warp = (blockIdx.x * blockDim.x + threadIdx.x) >> 5;
    int lane = threadIdx.x & 31;
    if (warp >= NN) return;
    int start = g_rowstart[warp];
    int n     = g_cnt[warp];
    float acc = 0.0f;
    for (int j = lane; j < n; j += 32)
        acc += g_s3[g_csrc[start + j]];
    #pragma unroll
    for (int o = 16; o > 0; o >>= 1) acc += __shfl_xor_sync(0xffffffffu, acc, o);
    if (lane == 0)
        out[warp] = fmaf(g_di[warp], acc + g_s3[warp], b3[0]);
}

// ---------------- mean pooling ----------------
__global__ void k_pool(const int* __restrict__ batch, const float* __restrict__ out) {
    __shared__ float ss[GG];
    __shared__ float sc[GG];
    int tid = threadIdx.x;
    if (tid < GG) { ss[tid] = 0.0f; sc[tid] = 0.0f; }
    __syncthreads();
    int i = blockIdx.x * blockDim.x + tid;
    if (i < NN) {
        int g = batch[i];
        atomicAdd(&ss[g], out[i]);
        atomicAdd(&sc[g], 1.0f);
    }
    __syncthreads();
    if (tid < GG) {
        if (ss[tid] != 0.0f || sc[tid] != 0.0f) {
            atomicAdd(&g_pool[tid], ss[tid]);
            atomicAdd(&g_pool[GG + tid], sc[tid]);
        }
    }
}

__global__ void k_final(const float* __restrict__ Wg, const float* __restrict__ bg,
                        float* __restrict__ out) {
    int g = threadIdx.x;
    if (g < GG) {
        float s = g_pool[g];
        float c = g_pool[GG + g];
        float p = s / fmaxf(c, 1.0f);
        out[NN + g] = fmaf(p, Wg[0], bg[0]);
    }
}

// ---------------- launcher ----------------
extern "C" void kernel_launch(void* const* d_in, const int* in_sizes, int n_in,
                              void* d_out, int out_size) {
    const float* x    = (const float*)d_in[0];
    const int*   ei   = (const int*)d_in[1];
    const int*   batch= (const int*)d_in[2];
    const float* W1   = (const float*)d_in[3];
    const float* b1   = (const float*)d_in[4];
    const float* g1   = (const float*)d_in[5];
    const float* be1  = (const float*)d_in[6];
    const float* W2   = (const float*)d_in[7];
    const float* b2   = (const float*)d_in[8];
    const float* g2   = (const float*)d_in[9];
    const float* be2  = (const float*)d_in[10];
    const float* W3   = (const float*)d_in[11];
    const float* b3   = (const float*)d_in[12];
    const float* Wg   = (const float*)d_in[13];
    const float* bg   = (const float*)d_in[14];
    const int* src = ei;
    const int* dst = ei + EE;
    float* out = (float*)d_out;

    float *bufA, *bufB;
    int* cntp;
    float* poolp;
    cudaGetSymbolAddress((void**)&bufA, g_bufA);
    cudaGetSymbolAddress((void**)&bufB, g_bufB);
    cudaGetSymbolAddress((void**)&cntp, g_cnt);
    cudaGetSymbolAddress((void**)&poolp, g_pool);

    // lazy one-time stream/event setup (host-side; created outside capture on
    // the first, non-captured correctness call and reused thereafter)
    static cudaStream_t s_side = nullptr;
    static cudaEvent_t  s_ev0  = nullptr;
    static cudaEvent_t  s_ev1  = nullptr;
    if (s_side == nullptr) {
        cudaStreamCreateWithFlags(&s_side, cudaStreamNonBlocking);
        cudaEventCreateWithFlags(&s_ev0, cudaEventDisableTiming);
        cudaEventCreateWithFlags(&s_ev1, cudaEventDisableTiming);
    }

    const int TB = 256;
    const int nblkN = NBLK_N;                  // 391
    const int nblkE = (EE + TB - 1) / TB;      // 6250
    const int nblkW = (NN * 32 + TB - 1) / TB; // 12500 warp-per-node
    const int nblkG = (NN + 63) / 64;          // 1563

    // zero counters (memset nodes)
    cudaMemsetAsync(cntp, 0, NN * sizeof(int), 0);
    cudaMemsetAsync(poolp, 0, 2 * GG * sizeof(float), 0);

    // degrees
    k_count<<<nblkE, TB>>>(dst);
    cudaEventRecord(s_ev0, 0);

    // side stream: CSR build (needs only counts)
    cudaStreamWaitEvent(s_side, s_ev0, 0);
    k_blocksum <<<nblkN, 256, 0, s_side>>>();
    k_scanblk  <<<1, 512, 0, s_side>>>();
    k_rowstart <<<nblkN, 256, 0, s_side>>>();
    k_fill     <<<nblkE, TB, 0, s_side>>>(src, dst);
    cudaEventRecord(s_ev1, s_side);

    // main stream: isqrt + layer-1 GEMM concurrent with CSR build
    k_isqrt<<<nblkN, TB>>>();
    k_gemm<IN_DIM><<<nblkG, TB>>>(x, W1, bufA);

    cudaStreamWaitEvent(0, s_ev1, 0);

    // layer 1 aggregation + LN + ReLU
    k_agg_ln<false><<<nblkW, TB>>>(bufA, bufB, b1, g1, be1, nullptr);

    // layer 2 (dot with W3 fused into the epilogue)
    k_gemm<HH><<<nblkG, TB>>>(bufB, W2, bufA);
    k_agg_ln<true><<<nblkW, TB>>>(bufA, nullptr, b2, g2, be2, W3);

    // layer 3 aggregation + pooling
    k_agg3 <<<nblkW, TB>>>(b3, out);
    k_pool <<<nblkN, TB>>>(batch, out);
    k_final<<<1, 64>>>(Wg, bg, out);
}

// round 4
// speedup vs baseline: 1.6518x; 1.0628x over previous
#include <cuda_runtime.h>
#include <cuda_bf16.h>
#include <cstdint>

#define NN 100000
#define EE 1600000
#define IN_DIM 128
#define HH 64
#define GG 64
#define LN_EPS 1e-5f

// ---------------- device scratch ----------------
struct Hdr {
    int   cnt[NN];       // in-degree counts
    int   total;         // scan ticket
    float pool[2 * GG];  // sums[G], counts[G]
};
__device__ Hdr   g_h;
__device__ int   g_rowstart[NN];
__device__ int   g_cur[NN];
__device__ int   g_csrc[EE];
__device__ float g_bufA[(size_t)NN * HH];
__device__ float g_bufB[(size_t)NN * HH];
__device__ float g_s3[NN];

// ---------------- setup ----------------
__global__ void k_count(const int* __restrict__ dst) {
    int e = blockIdx.x * blockDim.x + threadIdx.x;
    if (e < EE) atomicAdd(&g_h.cnt[dst[e]], 1);
}

// single-kernel exclusive scan: per-block local scan + atomic ticket for base
__global__ void k_scan() {
    __shared__ int s[256];
    __shared__ int base;
    int tid = threadIdx.x;
    int i = blockIdx.x * 256 + tid;
    int c = (i < NN) ? g_h.cnt[i] : 0;
    s[tid] = c;
    __syncthreads();
    #pragma unroll
    for (int o = 1; o < 256; o <<= 1) {
        int v = (tid >= o) ? s[tid - o] : 0;
        __syncthreads();
        s[tid] += v;
        __syncthreads();
    }
    if (tid == 255) base = atomicAdd(&g_h.total, s[255]);
    __syncthreads();
    int excl = s[tid] - c + base;
    if (i < NN) { g_rowstart[i] = excl; g_cur[i] = excl; }
}

__global__ void k_fill(const int* __restrict__ src, const int* __restrict__ dst) {
    int e = blockIdx.x * blockDim.x + threadIdx.x;
    if (e < EE) {
        int d = dst[e];
        int pos = atomicAdd(&g_cur[d], 1);
        g_csrc[pos] = src[e];
    }
}

// ------- GEMM: Y[N][64] = rsqrt(cnt+1)[row] * (X[N][K] @ W[K][64]) -------
template <int K>
__global__ __launch_bounds__(256) void k_gemm(const float* __restrict__ X,
                                              const float* __restrict__ W,
                                              float* __restrict__ Y) {
    __shared__ float  Xs[64][68];
    __shared__ float4 Ws[64][16];
    const int tid  = threadIdx.x;
    const int row0 = blockIdx.x * 64;
    const int tx = tid & 15;
    const int ty = tid >> 4;

    float4 acc[4];
    #pragma unroll
    for (int r = 0; r < 4; r++) acc[r] = make_float4(0.f, 0.f, 0.f, 0.f);

    for (int kk = 0; kk < K; kk += 64) {
        #pragma unroll
        for (int i = tid; i < 1024; i += 256) {
            int k = i >> 4, c = i & 15;
            Ws[k][c] = reinterpret_cast<const float4*>(W)[(size_t)(kk + k) * 16 + c];
        }
        #pragma unroll
        for (int i = tid; i < 1024; i += 256) {
            int r = i >> 4, kv = i & 15;
            int row = row0 + r;
            float4 v = make_float4(0.f, 0.f, 0.f, 0.f);
            if (row < NN)
                v = reinterpret_cast<const float4*>(X)[(size_t)row * (K / 4) + (kk / 4) + kv];
            *reinterpret_cast<float4*>(&Xs[r][kv * 4]) = v;
        }
        __syncthreads();

        #pragma unroll 16
        for (int k = 0; k < 64; k++) {
            float4 w = Ws[k][tx];
            #pragma unroll
            for (int r = 0; r < 4; r++) {
                float xv = Xs[ty * 4 + r][k];
                acc[r].x = fmaf(xv, w.x, acc[r].x);
                acc[r].y = fmaf(xv, w.y, acc[r].y);
                acc[r].z = fmaf(xv, w.z, acc[r].z);
                acc[r].w = fmaf(xv, w.w, acc[r].w);
            }
        }
        __syncthreads();
    }

    #pragma unroll
    for (int r = 0; r < 4; r++) {
        int row = row0 + ty * 4 + r;
        if (row < NN) {
            float d = rsqrtf((float)g_h.cnt[row] + 1.0f);
            float4 a = acc[r];
            a.x *= d; a.y *= d; a.z *= d; a.w *= d;
            reinterpret_cast<float4*>(Y)[(size_t)row * 16 + tx] = a;
        }
    }
}

// ------- fused gather + self + di-postscale + bias + LN + ReLU (+ optional W3 dot) -------
// warp per dst node; lane owns features (2*lane, 2*lane+1) via float2
template <bool FUSE_DOT>
__global__ __launch_bounds__(256) void k_agg_ln(const float* __restrict__ hs,
                                                float* __restrict__ Yout,
                                                const float* __restrict__ b,
                                                const float* __restrict__ gam,
                                                const float* __restrict__ bet,
                                                const float* __restrict__ W3) {
    int warp = (blockIdx.x * blockDim.x + threadIdx.x) >> 5;
    int lane = threadIdx.x & 31;
    if (warp >= NN) return;

    const int start = g_rowstart[warp];
    const int n     = g_h.cnt[warp];
    const float2* __restrict__ hp = reinterpret_cast<const float2*>(hs);

    float2 self = hp[(size_t)warp * 32 + lane];
    float a0 = self.x;
    float a1 = self.y;

    int j = 0;
    while (j + 32 <= n) {
        int idx = g_csrc[start + j + lane];
        #pragma unroll 8
        for (int t = 0; t < 32; t++) {
            int s = __shfl_sync(0xffffffffu, idx, t);
            float2 v = hp[(size_t)s * 32 + lane];
            a0 += v.x;
            a1 += v.y;
        }
        j += 32;
    }
    if (j < n) {
        int m = n - j;
        int idx = (j + lane < n) ? g_csrc[start + j + lane] : 0;
        #pragma unroll 4
        for (int t = 0; t < m; t++) {
            int s = __shfl_sync(0xffffffffu, idx, t);
            float2 v = hp[(size_t)s * 32 + lane];
            a0 += v.x;
            a1 += v.y;
        }
    }

    float dd = rsqrtf((float)n + 1.0f);
    float2 bv = reinterpret_cast<const float2*>(b)[lane];
    float x0 = fmaf(dd, a0, bv.x);
    float x1 = fmaf(dd, a1, bv.y);

    float s  = x0 + x1;
    float q  = x0 * x0 + x1 * x1;
    #pragma unroll
    for (int o = 16; o > 0; o >>= 1) {
        s += __shfl_xor_sync(0xffffffffu, s, o);
        q += __shfl_xor_sync(0xffffffffu, q, o);
    }
    float mu  = s * (1.0f / 64.0f);
    float var = q * (1.0f / 64.0f) - mu * mu;
    float rs  = rsqrtf(var + LN_EPS);
    float2 gv = reinterpret_cast<const float2*>(gam)[lane];
    float2 ev = reinterpret_cast<const float2*>(bet)[lane];
    float y0 = fmaxf(fmaf((x0 - mu) * rs, gv.x, ev.x), 0.0f);
    float y1 = fmaxf(fmaf((x1 - mu) * rs, gv.y, ev.y), 0.0f);

    if (FUSE_DOT) {
        float2 wv = reinterpret_cast<const float2*>(W3)[lane];
        float p = y0 * wv.x + y1 * wv.y;
        #pragma unroll
        for (int o = 16; o > 0; o >>= 1) p += __shfl_xor_sync(0xffffffffu, p, o);
        if (lane == 0) g_s3[warp] = p * dd;
    } else {
        float2 yv = make_float2(y0, y1);
        reinterpret_cast<float2*>(Yout)[(size_t)warp * 32 + lane] = yv;
    }
}

// out[i] = di[i] * (sum_neighbors s3[src] + s3[i]) + b3
__global__ void k_agg3(const float* __restrict__ b3, float* __restrict__ out) {
    int warp = (blockIdx.x * blockDim.x + threadIdx.x) >> 5;
    int lane = threadIdx.x & 31;
    if (warp >= NN) return;
    int start = g_rowstart[warp];
    int n     = g_h.cnt[warp];
    float acc = 0.0f;
    for (int j = lane; j < n; j += 32)
        acc += g_s3[g_csrc[start + j]];
    #pragma unroll
    for (int o = 16; o > 0; o >>= 1) acc += __shfl_xor_sync(0xffffffffu, acc, o);
    if (lane == 0) {
        float dd = rsqrtf((float)n + 1.0f);
        out[warp] = fmaf(dd, acc + g_s3[warp], b3[0]);
    }
}

// ---------------- mean pooling ----------------
__global__ void k_pool(const int* __restrict__ batch, const float* __restrict__ out) {
    __shared__ float ss[GG];
    __shared__ float sc[GG];
    int tid = threadIdx.x;
    if (tid < GG) { ss[tid] = 0.0f; sc[tid] = 0.0f; }
    __syncthreads();
    int i = blockIdx.x * blockDim.x + tid;
    if (i < NN) {
        int g = batch[i];
        atomicAdd(&ss[g], out[i]);
        atomicAdd(&sc[g], 1.0f);
    }
    __syncthreads();
    if (tid < GG) {
        if (ss[tid] != 0.0f || sc[tid] != 0.0f) {
            atomicAdd(&g_h.pool[tid], ss[tid]);
            atomicAdd(&g_h.pool[GG + tid], sc[tid]);
        }
    }
}

__global__ void k_final(const float* __restrict__ Wg, const float* __restrict__ bg,
                        float* __restrict__ out) {
    int g = threadIdx.x;
    if (g < GG) {
        float s = g_h.pool[g];
        float c = g_h.pool[GG + g];
        float p = s / fmaxf(c, 1.0f);
        out[NN + g] = fmaf(p, Wg[0], bg[0]);
    }
}

// ---------------- launcher ----------------
extern "C" void kernel_launch(void* const* d_in, const int* in_sizes, int n_in,
                              void* d_out, int out_size) {
    const float* x    = (const float*)d_in[0];
    const int*   ei   = (const int*)d_in[1];
    const int*   batch= (const int*)d_in[2];
    const float* W1   = (const float*)d_in[3];
    const float* b1   = (const float*)d_in[4];
    const float* g1   = (const float*)d_in[5];
    const float* be1  = (const float*)d_in[6];
    const float* W2   = (const float*)d_in[7];
    const float* b2   = (const float*)d_in[8];
    const float* g2   = (const float*)d_in[9];
    const float* be2  = (const float*)d_in[10];
    const float* W3   = (const float*)d_in[11];
    const float* b3   = (const float*)d_in[12];
    const float* Wg   = (const float*)d_in[13];
    const float* bg   = (const float*)d_in[14];
    const int* src = ei;
    const int* dst = ei + EE;
    float* out = (float*)d_out;

    float *bufA, *bufB;
    void* hdrp;
    cudaGetSymbolAddress((void**)&bufA, g_bufA);
    cudaGetSymbolAddress((void**)&bufB, g_bufB);
    cudaGetSymbolAddress(&hdrp, g_h);

    static cudaStream_t s_side = nullptr;
    static cudaEvent_t  s_ev0  = nullptr;
    static cudaEvent_t  s_ev1  = nullptr;
    if (s_side == nullptr) {
        cudaStreamCreateWithFlags(&s_side, cudaStreamNonBlocking);
        cudaEventCreateWithFlags(&s_ev0, cudaEventDisableTiming);
        cudaEventCreateWithFlags(&s_ev1, cudaEventDisableTiming);
    }

    const int TB = 256;
    const int nblkN = (NN + TB - 1) / TB;      // 391
    const int nblkE = (EE + TB - 1) / TB;      // 6250
    const int nblkW = (NN * 32 + TB - 1) / TB; // 12500 warp-per-node
    const int nblkG = (NN + 63) / 64;          // 1563

    // zero counters + ticket + pool in one memset
    cudaMemsetAsync(hdrp, 0, sizeof(Hdr), 0);

    // degrees
    k_count<<<nblkE, TB>>>(dst);
    cudaEventRecord(s_ev0, 0);

    // side stream: CSR build (offsets + fill)
    cudaStreamWaitEvent(s_side, s_ev0, 0);
    k_scan<<<nblkN, 256, 0, s_side>>>();
    k_fill<<<nblkE, TB, 0, s_side>>>(src, dst);
    cudaEventRecord(s_ev1, s_side);

    // main stream: layer-1 GEMM concurrent with CSR build
    k_gemm<IN_DIM><<<nblkG, TB>>>(x, W1, bufA);
    cudaStreamWaitEvent(0, s_ev1, 0);

    // layer 1 aggregation + LN + ReLU
    k_agg_ln<false><<<nblkW, TB>>>(bufA, bufB, b1, g1, be1, nullptr);

    // layer 2 (W3 dot fused into epilogue)
    k_gemm<HH><<<nblkG, TB>>>(bufB, W2, bufA);
    k_agg_ln<true><<<nblkW, TB>>>(bufA, nullptr, b2, g2, be2, W3);

    // layer 3 aggregation + pooling
    k_agg3 <<<nblkW, TB>>>(b3, out);
    k_pool <<<nblkN, TB>>>(batch, out);
    k_final<<<1, 64>>>(Wg, bg, out);
}